// round 10
// baseline (speedup 1.0000x reference)
#include <cuda_runtime.h>
#include <cuda_bf16.h>
#include <cstdint>

typedef unsigned long long ull;

// Problem constants
#define BB   16
#define TT   2048
#define DD   512
#define GG   2048           // 4*D
#define NC   128            // scan CTAs (each owns D/NC = 4 hidden units)
#define SCAN_THREADS 256
#define BAR_SLOTS 8         // arrival counters per step
#define BAR_STRIDE 64       // ints between counters (256 B -> distinct L2 lines/slices)

// ---- packed fp32x2 helpers (sm_103a dual-fp32 pipe) ----
__device__ __forceinline__ ull fma2(ull a, ull b, ull c) {
    ull d;
    asm("fma.rn.f32x2 %0, %1, %2, %3;" : "=l"(d) : "l"(a), "l"(b), "l"(c));
    return d;
}
__device__ __forceinline__ ull add2(ull a, ull b) {
    ull d;
    asm("add.rn.f32x2 %0, %1, %2;" : "=l"(d) : "l"(a), "l"(b));
    return d;
}
__device__ __forceinline__ ull pack2(float lo, float hi) {
    ull d;
    asm("mov.b64 %0, {%1, %2};" : "=l"(d) : "f"(lo), "f"(hi));
    return d;
}
__device__ __forceinline__ float2 unpack2(ull a) {
    float2 f;
    asm("mov.b64 {%0, %1}, %2;" : "=f"(f.x), "=f"(f.y) : "l"(a));
    return f;
}

// Fast, overflow-safe nonlinearities (MUFU-based; err ~1e-7)
__device__ __forceinline__ float fast_sigmoid(float x) {
    return __fdividef(1.f, 1.f + __expf(-x));   // exp(-x)->inf only for x<<0 -> 0 (correct limit)
}
__device__ __forceinline__ float fast_tanh(float x) {
    float e = __expf(-2.f * fabsf(x));          // in (0,1], never overflows
    float r = __fdividef(1.f - e, 1.f + e);
    return copysignf(r, x);
}

// Scratch (device globals: sanctioned allocation-free workaround)
__device__ float g_xg[(size_t)TT * BB * GG];   // [T][B][G]
__device__ float g_Y0[(size_t)BB * TT * DD];
__device__ float g_Y1[(size_t)BB * TT * DD];
__device__ float g_H[2 * DD * BB];             // [buf][d][b]  (transposed)
__device__ __align__(256) int g_bar[(size_t)TT * BAR_SLOTS * BAR_STRIDE];  // per-step counters

// ---------------------------------------------------------------------------
// GEMM: C[t][b][e] = sum_d A[b][t][d] * W[d][e] + bias[e]
// 128x128 tile, BK=8, 256 threads, 8x8 microtile, f32x2-packed FMAs.
// ---------------------------------------------------------------------------
__global__ __launch_bounds__(256, 2)
void gemm_xw(const float* __restrict__ A,    // [B][T][D]
             const float* __restrict__ W,    // [D][G]
             const float* __restrict__ bias, // [G]
             float* __restrict__ C)          // [T][B][G]
{
    const int bz   = blockIdx.z;
    const int row0 = blockIdx.y * 128;   // t
    const int col0 = blockIdx.x * 128;   // e
    const float* Ab = A + (size_t)bz * TT * DD;

    __shared__ float As[8][128];
    __shared__ float Ws[8][128];

    const int tid = threadIdx.x;
    const int tx = tid & 15;
    const int ty = tid >> 4;

    const int am = tid >> 1;
    const int ak = (tid & 1) * 4;
    const int kw = tid >> 5;
    const int nw = (tid & 31) * 4;

    ull acc2[8][4];
#pragma unroll
    for (int i = 0; i < 8; i++)
#pragma unroll
        for (int j = 0; j < 4; j++) acc2[i][j] = 0ull;

    for (int kb = 0; kb < DD; kb += 8) {
        float4 av = *(const float4*)&Ab[(size_t)(row0 + am) * DD + kb + ak];
        float4 wv = *(const float4*)&W[(size_t)(kb + kw) * GG + col0 + nw];
        __syncthreads();
        As[ak + 0][am] = av.x;
        As[ak + 1][am] = av.y;
        As[ak + 2][am] = av.z;
        As[ak + 3][am] = av.w;
        *(float4*)&Ws[kw][nw] = wv;
        __syncthreads();
#pragma unroll
        for (int k = 0; k < 8; k++) {
            float a0[8];
            *(float4*)&a0[0] = *(const float4*)&As[k][ty * 4];
            *(float4*)&a0[4] = *(const float4*)&As[k][64 + ty * 4];
            ull b2[4];
            b2[0] = *(const ull*)&Ws[k][tx * 4];
            b2[1] = *(const ull*)&Ws[k][tx * 4 + 2];
            b2[2] = *(const ull*)&Ws[k][64 + tx * 4];
            b2[3] = *(const ull*)&Ws[k][64 + tx * 4 + 2];
#pragma unroll
            for (int i = 0; i < 8; i++) {
                ull as = pack2(a0[i], a0[i]);
#pragma unroll
                for (int j = 0; j < 4; j++)
                    acc2[i][j] = fma2(as, b2[j], acc2[i][j]);
            }
        }
    }

    float4 bias0 = *(const float4*)&bias[col0 + tx * 4];
    float4 bias1 = *(const float4*)&bias[col0 + 64 + tx * 4];

#pragma unroll
    for (int i = 0; i < 8; i++) {
        int m = row0 + ((i < 4) ? (ty * 4 + i) : (64 + ty * 4 + i - 4));
        size_t base = ((size_t)m * BB + bz) * GG + col0;
        float2 p0 = unpack2(acc2[i][0]);
        float2 p1 = unpack2(acc2[i][1]);
        float2 p2 = unpack2(acc2[i][2]);
        float2 p3 = unpack2(acc2[i][3]);
        float4 v0, v1;
        v0.x = p0.x + bias0.x; v0.y = p0.y + bias0.y;
        v0.z = p1.x + bias0.z; v0.w = p1.y + bias0.w;
        v1.x = p2.x + bias1.x; v1.y = p2.y + bias1.y;
        v1.z = p3.x + bias1.z; v1.w = p3.y + bias1.w;
        *(float4*)&C[base + tx * 4]      = v0;
        *(float4*)&C[base + 64 + tx * 4] = v1;
    }
}

// ---------------------------------------------------------------------------
// Persistent LSTM scan. 128 CTAs; CTA owns 4 hidden units = 16 gate columns.
// Thread tile: 8 cols x 4 batches, k split 32 ways (proven R6 layout).
// Barrier: per-step counters split over 8 addresses (256B apart); CTA c arrives
// on slot (c&7) via atomicAdd (RED), warp 0 polls all 8 slots (target 16 each).
// ---------------------------------------------------------------------------
#define SW 18   // Whs row stride (floats)
#define SH 24   // Hs  row stride (floats)

__global__ __launch_bounds__(SCAN_THREADS, 1)
void lstm_scan(const float* __restrict__ xg,   // [T][B][G]
               const float* __restrict__ Whl,  // [D][G]
               float* __restrict__ Y,          // [B][T][D]
               float* __restrict__ Hbuf,       // [2][D][B]
               int* __restrict__ bar)          // [TT][8][64]
{
    extern __shared__ float sm[];
    float* Whs = sm;                           // 512*18
    float* Hs  = Whs + 512 * SW;               // 512*24
    ull*   red = (ull*)(Hs + 512 * SH);        // 8*8*17 ull
    float* gsm = (float*)(red + 8 * 8 * 17);   // 16*16
    float* csm = gsm + 256;                    // 64

    const int tid  = threadIdx.x;
    const int cta  = blockIdx.x;
    const int lane = tid & 31;
    const int wid  = tid >> 5;
    const int ks   = tid >> 3;                 // kslice 0..31
    const int grp  = tid & 7;
    const int cg   = grp >> 2;                 // 0..1
    const int bg   = grp & 3;                  // 0..3

    // One-time: Wh slice into SMEM as [k][16 local cols]
    for (int idx = tid; idx < 512 * 16; idx += SCAN_THREADS) {
        int k = idx >> 4, c = idx & 15;
        Whs[k * SW + c] = Whl[(size_t)k * GG + (c >> 2) * DD + cta * 4 + (c & 3)];
    }
    if (tid < 64) csm[tid] = 0.f;
    __syncthreads();

    const int wbase = ks * SW + cg * 8;
    const int hbase = ks * SH + bg * 4;

    // reducer identity (tid < 128)
    const int cp  = tid >> 4;                  // col-pair 0..7
    const int rb  = tid & 15;                  // batch
    const int rgrp  = ((cp >> 2) * 4) + (rb >> 2);
    const int rslot = (cp & 3) * 4 + (rb & 3);
    const size_t xgoff = (cp >> 1) * DD + cta * 4 + (cp & 1) * 2;

    const int myslot = (cta & 7) * BAR_STRIDE;

    for (int t = 0; t < TT; t++) {
        // prefetch xg pair for reducers
        ull xg2 = 0;
        if (tid < 128)
            xg2 = *(const ull*)&xg[((size_t)t * BB + rb) * GG + xgoff];

        // gather H(t-1) [d][b] from L2 into Hs[k][b] (stride 24)
        const float4* Hr = (const float4*)(Hbuf + ((t + 1) & 1) * (DD * BB));
#pragma unroll
        for (int j = 0; j < 8; j++) {
            int i4 = tid + j * SCAN_THREADS;   // 0..2047
            float4 v = __ldcg(Hr + i4);
            *(float4*)&Hs[(i4 >> 2) * SH + (i4 & 3) * 4] = v;
        }
        __syncthreads();

        // dot: acc[j][bi] (cols cg*8+2j,+1  x  batch bg*4+bi), k = kk*32+ks
        ull acc[16];
#pragma unroll
        for (int i = 0; i < 16; i++) acc[i] = 0ull;

#pragma unroll
        for (int kk = 0; kk < 16; kk++) {
            const float* wr = &Whs[wbase + kk * (32 * SW)];
            const float* hr = &Hs[hbase + kk * (32 * SH)];
            ull w0 = *(const ull*)(wr + 0);
            ull w1 = *(const ull*)(wr + 2);
            ull w2 = *(const ull*)(wr + 4);
            ull w3 = *(const ull*)(wr + 6);
            ull h0 = pack2(hr[0], hr[0]);
            ull h1 = pack2(hr[1], hr[1]);
            ull h2 = pack2(hr[2], hr[2]);
            ull h3 = pack2(hr[3], hr[3]);
            acc[0]  = fma2(w0, h0, acc[0]);
            acc[1]  = fma2(w0, h1, acc[1]);
            acc[2]  = fma2(w0, h2, acc[2]);
            acc[3]  = fma2(w0, h3, acc[3]);
            acc[4]  = fma2(w1, h0, acc[4]);
            acc[5]  = fma2(w1, h1, acc[5]);
            acc[6]  = fma2(w1, h2, acc[6]);
            acc[7]  = fma2(w1, h3, acc[7]);
            acc[8]  = fma2(w2, h0, acc[8]);
            acc[9]  = fma2(w2, h1, acc[9]);
            acc[10] = fma2(w2, h2, acc[10]);
            acc[11] = fma2(w2, h3, acc[11]);
            acc[12] = fma2(w3, h0, acc[12]);
            acc[13] = fma2(w3, h1, acc[13]);
            acc[14] = fma2(w3, h2, acc[14]);
            acc[15] = fma2(w3, h3, acc[15]);
        }

        // reduce 4 kslices within warp (kslice low bits = lane bits 3,4)
#pragma unroll
        for (int i = 0; i < 16; i++) {
            acc[i] = add2(acc[i], __shfl_xor_sync(0xffffffffu, acc[i], 8));
            acc[i] = add2(acc[i], __shfl_xor_sync(0xffffffffu, acc[i], 16));
        }
        if (lane < 8) {
#pragma unroll
            for (int i = 0; i < 16; i++)
                red[(wid * 8 + grp) * 17 + ((i >> 2) * 4 + (i & 3))] = acc[i];
        }
        __syncthreads();

        // cross-warp reduce: 128 threads, one col-pair x batch each
        if (tid < 128) {
            ull s = red[rgrp * 17 + rslot];
#pragma unroll
            for (int w = 1; w < 8; w++)
                s = add2(s, red[(w * 8 + rgrp) * 17 + rslot]);
            s = add2(s, xg2);
            float2 g = unpack2(s);
            gsm[(2 * cp) * 16 + rb]     = g.x;
            gsm[(2 * cp + 1) * 16 + rb] = g.y;
        }
        __syncthreads();

        // gates + state update (64 threads: 4 hidden x 16 batch)
        float hval = 0.f;
        int   dg   = 0, bb = 0;
        if (tid < 64) {
            int d2 = tid >> 4; bb = tid & 15;
            float gi = gsm[(0 * 4 + d2) * 16 + bb];
            float gf = gsm[(1 * 4 + d2) * 16 + bb];
            float gg = gsm[(2 * 4 + d2) * 16 + bb];
            float go = gsm[(3 * 4 + d2) * 16 + bb];
            float iv = fast_sigmoid(gi);
            float fv = fast_sigmoid(gf);
            float gv = fast_tanh(gg);
            float ov = fast_sigmoid(go);
            float c = fv * csm[tid] + iv * gv;
            csm[tid] = c;
            hval = ov * fast_tanh(c);
            dg = cta * 4 + d2;
            Hbuf[(t & 1) * (DD * BB) + dg * BB + bb] = hval;   // [d][b]
            __threadfence();   // push h to L2 before the arrive
        }
        __syncthreads();

        int* barT = bar + (size_t)t * (BAR_SLOTS * BAR_STRIDE);

        // arrive: 16 CTAs per counter, 8 counters on distinct L2 lines
        if (tid == 0) atomicAdd(&barT[myslot], 1);

        // Y store off the critical path
        if (tid < 64)
            Y[((size_t)bb * TT + t) * DD + dg] = hval;

        // warp 0 polls all 8 counters (8 lanes, distinct lines)
        if (wid == 0) {
            int done;
            do {
                int v = (lane < BAR_SLOTS)
                          ? *(volatile int*)&barT[lane * BAR_STRIDE]
                          : (NC / BAR_SLOTS);
                done = __all_sync(0xffffffffu, v >= (NC / BAR_SLOTS));
            } while (!done);
        }
        __syncthreads();
    }
}

// ---------------------------------------------------------------------------
__global__ __launch_bounds__(256)
void add_skip(const float* __restrict__ a, const float* __restrict__ x,
              float* __restrict__ out, int n4)
{
    int i = blockIdx.x * blockDim.x + threadIdx.x;
    if (i < n4) {
        float4 va = ((const float4*)a)[i];
        float4 vx = ((const float4*)x)[i];
        float4 r;
        r.x = va.x + vx.x; r.y = va.y + vx.y;
        r.z = va.z + vx.z; r.w = va.w + vx.w;
        ((float4*)out)[i] = r;
    }
}

// ---------------------------------------------------------------------------
extern "C" void kernel_launch(void* const* d_in, const int* in_sizes, int n_in,
                              void* d_out, int out_size)
{
    const float* x    = (const float*)d_in[0];  // [B][T][D]
    const float* Wx   = (const float*)d_in[1];  // [L][D][4D]
    const float* Wh   = (const float*)d_in[2];  // [L][D][4D]
    const float* bias = (const float*)d_in[3];  // [L][4D]
    float* out = (float*)d_out;

    const int smem_scan = (512 * SW + 512 * SH + 2 * (8 * 8 * 17) + 256 + 64) * 4;
    cudaFuncSetAttribute(lstm_scan, cudaFuncAttributeMaxDynamicSharedMemorySize, smem_scan);

    void *xg_p, *y0_p, *y1_p, *h_p, *bar_p;
    cudaGetSymbolAddress(&xg_p, g_xg);
    cudaGetSymbolAddress(&y0_p, g_Y0);
    cudaGetSymbolAddress(&y1_p, g_Y1);
    cudaGetSymbolAddress(&h_p,  g_H);
    cudaGetSymbolAddress(&bar_p, g_bar);
    float* XG = (float*)xg_p;
    float* Y0 = (float*)y0_p;
    float* Y1 = (float*)y1_p;
    float* Hb = (float*)h_p;
    int*  BAR = (int*)bar_p;

    const size_t bar_bytes = (size_t)TT * BAR_SLOTS * BAR_STRIDE * sizeof(int);

    dim3 gg(GG / 128, TT / 128, BB);   // (16,16,16)

    // ---- layer 0 ----
    gemm_xw<<<gg, 256>>>(x, Wx, bias, XG);
    cudaMemsetAsync(BAR, 0, bar_bytes, 0);
    cudaMemsetAsync(Hb, 0, 2 * DD * BB * sizeof(float), 0);
    lstm_scan<<<NC, SCAN_THREADS, smem_scan>>>(XG, Wh, Y0, Hb, BAR);

    // ---- layer 1 ----
    gemm_xw<<<gg, 256>>>(Y0, Wx + (size_t)DD * GG, bias + GG, XG);
    cudaMemsetAsync(BAR, 0, bar_bytes, 0);
    cudaMemsetAsync(Hb, 0, 2 * DD * BB * sizeof(float), 0);
    lstm_scan<<<NC, SCAN_THREADS, smem_scan>>>(XG, Wh + (size_t)DD * GG, Y1, Hb, BAR);

    // ---- residual skip ----
    int n4 = (BB * TT * DD) / 4;
    add_skip<<<n4 / 256, 256>>>(Y1, x, out, n4);
}

// round 13
// speedup vs baseline: 1.0720x; 1.0720x over previous
#include <cuda_runtime.h>
#include <cuda_bf16.h>
#include <cstdint>

typedef unsigned long long ull;

// Problem constants
#define BB   16
#define TT   2048
#define DD   512
#define GG   2048           // 4*D
#define NC   128            // scan CTAs (each owns D/NC = 4 hidden units)
#define SCAN_THREADS 256
#define BAR_SLOTS 8
#define BAR_STRIDE 64       // ints between counters (256 B)

// ---- packed fp32x2 helpers (sm_103a dual-fp32 pipe) ----
__device__ __forceinline__ ull fma2(ull a, ull b, ull c) {
    ull d;
    asm("fma.rn.f32x2 %0, %1, %2, %3;" : "=l"(d) : "l"(a), "l"(b), "l"(c));
    return d;
}
__device__ __forceinline__ ull add2(ull a, ull b) {
    ull d;
    asm("add.rn.f32x2 %0, %1, %2;" : "=l"(d) : "l"(a), "l"(b));
    return d;
}
__device__ __forceinline__ ull pack2(float lo, float hi) {
    ull d;
    asm("mov.b64 %0, {%1, %2};" : "=l"(d) : "f"(lo), "f"(hi));
    return d;
}
__device__ __forceinline__ float2 unpack2(ull a) {
    float2 f;
    asm("mov.b64 {%0, %1}, %2;" : "=f"(f.x), "=f"(f.y) : "l"(a));
    return f;
}

// Fast, overflow-safe nonlinearities (MUFU-based; err ~1e-7)
__device__ __forceinline__ float fast_sigmoid(float x) {
    return __fdividef(1.f, 1.f + __expf(-x));
}
__device__ __forceinline__ float fast_tanh(float x) {
    float e = __expf(-2.f * fabsf(x));
    float r = __fdividef(1.f - e, 1.f + e);
    return copysignf(r, x);
}

// Scratch (device globals: sanctioned allocation-free workaround)
__device__ float g_xg[(size_t)TT * BB * GG];   // [T][B][G]
__device__ float g_Y0[(size_t)BB * TT * DD];
__device__ float g_Y1[(size_t)BB * TT * DD];
__device__ float g_H[2 * DD * BB];             // [buf][d][b]
__device__ __align__(256) int g_bar[(size_t)TT * BAR_SLOTS * BAR_STRIDE];

// ---------------------------------------------------------------------------
// GEMM: C[t][b][e] = sum_d A[b][t][d] * W[d][e] + bias[e]
// ---------------------------------------------------------------------------
__global__ __launch_bounds__(256, 2)
void gemm_xw(const float* __restrict__ A,
             const float* __restrict__ W,
             const float* __restrict__ bias,
             float* __restrict__ C)
{
    const int bz   = blockIdx.z;
    const int row0 = blockIdx.y * 128;
    const int col0 = blockIdx.x * 128;
    const float* Ab = A + (size_t)bz * TT * DD;

    __shared__ float As[8][128];
    __shared__ float Ws[8][128];

    const int tid = threadIdx.x;
    const int tx = tid & 15;
    const int ty = tid >> 4;

    const int am = tid >> 1;
    const int ak = (tid & 1) * 4;
    const int kw = tid >> 5;
    const int nw = (tid & 31) * 4;

    ull acc2[8][4];
#pragma unroll
    for (int i = 0; i < 8; i++)
#pragma unroll
        for (int j = 0; j < 4; j++) acc2[i][j] = 0ull;

    for (int kb = 0; kb < DD; kb += 8) {
        float4 av = *(const float4*)&Ab[(size_t)(row0 + am) * DD + kb + ak];
        float4 wv = *(const float4*)&W[(size_t)(kb + kw) * GG + col0 + nw];
        __syncthreads();
        As[ak + 0][am] = av.x;
        As[ak + 1][am] = av.y;
        As[ak + 2][am] = av.z;
        As[ak + 3][am] = av.w;
        *(float4*)&Ws[kw][nw] = wv;
        __syncthreads();
#pragma unroll
        for (int k = 0; k < 8; k++) {
            float a0[8];
            *(float4*)&a0[0] = *(const float4*)&As[k][ty * 4];
            *(float4*)&a0[4] = *(const float4*)&As[k][64 + ty * 4];
            ull b2[4];
            b2[0] = *(const ull*)&Ws[k][tx * 4];
            b2[1] = *(const ull*)&Ws[k][tx * 4 + 2];
            b2[2] = *(const ull*)&Ws[k][64 + tx * 4];
            b2[3] = *(const ull*)&Ws[k][64 + tx * 4 + 2];
#pragma unroll
            for (int i = 0; i < 8; i++) {
                ull as = pack2(a0[i], a0[i]);
#pragma unroll
                for (int j = 0; j < 4; j++)
                    acc2[i][j] = fma2(as, b2[j], acc2[i][j]);
            }
        }
    }

    float4 bias0 = *(const float4*)&bias[col0 + tx * 4];
    float4 bias1 = *(const float4*)&bias[col0 + 64 + tx * 4];

#pragma unroll
    for (int i = 0; i < 8; i++) {
        int m = row0 + ((i < 4) ? (ty * 4 + i) : (64 + ty * 4 + i - 4));
        size_t base = ((size_t)m * BB + bz) * GG + col0;
        float2 p0 = unpack2(acc2[i][0]);
        float2 p1 = unpack2(acc2[i][1]);
        float2 p2 = unpack2(acc2[i][2]);
        float2 p3 = unpack2(acc2[i][3]);
        float4 v0, v1;
        v0.x = p0.x + bias0.x; v0.y = p0.y + bias0.y;
        v0.z = p1.x + bias0.z; v0.w = p1.y + bias0.w;
        v1.x = p2.x + bias1.x; v1.y = p2.y + bias1.y;
        v1.z = p3.x + bias1.z; v1.w = p3.y + bias1.w;
        *(float4*)&C[base + tx * 4]      = v0;
        *(float4*)&C[base + 64 + tx * 4] = v1;
    }
}

// ---------------------------------------------------------------------------
// Persistent LSTM scan (R10 skeleton). New: Y buffered in smem, flushed
// coalesced every 8 steps between barrier-arrive and poll.
// ---------------------------------------------------------------------------
#define SW 18   // Whs row stride (floats)
#define SH 24   // Hs  row stride (floats)

__global__ __launch_bounds__(SCAN_THREADS, 1)
void lstm_scan(const float* __restrict__ xg,   // [T][B][G]
               const float* __restrict__ Whl,  // [D][G]
               float* __restrict__ Y,          // [B][T][D]
               float* __restrict__ Hbuf,       // [2][D][B]
               int* __restrict__ bar)          // [TT][8][64]
{
    extern __shared__ float sm[];
    float* Whs  = sm;                           // 512*18
    float* Hs   = Whs + 512 * SW;               // 512*24
    ull*   red  = (ull*)(Hs + 512 * SH);        // 8*8*17 ull
    float* gsm  = (float*)(red + 8 * 8 * 17);   // 16*16
    float* csm  = gsm + 256;                    // 64
    float* Ybuf = csm + 64;                     // 8*16*4 = 512 floats (2KB)

    const int tid  = threadIdx.x;
    const int cta  = blockIdx.x;
    const int lane = tid & 31;
    const int wid  = tid >> 5;
    const int ks   = tid >> 3;                 // kslice 0..31
    const int grp  = tid & 7;
    const int cg   = grp >> 2;
    const int bg   = grp & 3;

    // One-time: Wh slice into SMEM as [k][16 local cols]
    for (int idx = tid; idx < 512 * 16; idx += SCAN_THREADS) {
        int k = idx >> 4, c = idx & 15;
        Whs[k * SW + c] = Whl[(size_t)k * GG + (c >> 2) * DD + cta * 4 + (c & 3)];
    }
    if (tid < 64) csm[tid] = 0.f;
    __syncthreads();

    const int wbase = ks * SW + cg * 8;
    const int hbase = ks * SH + bg * 4;

    // reducer identity (tid < 128)
    const int cp  = tid >> 4;                  // col-pair 0..7
    const int rb  = tid & 15;                  // batch
    const int rgrp  = ((cp >> 2) * 4) + (rb >> 2);
    const int rslot = (cp & 3) * 4 + (rb & 3);
    const size_t xgoff = (cp >> 1) * DD + cta * 4 + (cp & 1) * 2;

    const int myslot = (cta & 7) * BAR_STRIDE;

    // Y-flush identity (tid < 128): j = step-in-window, fb = batch
    const int fj = tid >> 4;                   // 0..7
    const int fb = tid & 15;

    for (int t = 0; t < TT; t++) {
        // prefetch xg pair for reducers
        ull xg2 = 0;
        if (tid < 128)
            xg2 = *(const ull*)&xg[((size_t)t * BB + rb) * GG + xgoff];

        // gather H(t-1) [d][b] from L2 into Hs[k][b]
        const float4* Hr = (const float4*)(Hbuf + ((t + 1) & 1) * (DD * BB));
#pragma unroll
        for (int j = 0; j < 8; j++) {
            int i4 = tid + j * SCAN_THREADS;
            float4 v = __ldcg(Hr + i4);
            *(float4*)&Hs[(i4 >> 2) * SH + (i4 & 3) * 4] = v;
        }
        __syncthreads();

        // dot
        ull acc[16];
#pragma unroll
        for (int i = 0; i < 16; i++) acc[i] = 0ull;

#pragma unroll
        for (int kk = 0; kk < 16; kk++) {
            const float* wr = &Whs[wbase + kk * (32 * SW)];
            const float* hr = &Hs[hbase + kk * (32 * SH)];
            ull w0 = *(const ull*)(wr + 0);
            ull w1 = *(const ull*)(wr + 2);
            ull w2 = *(const ull*)(wr + 4);
            ull w3 = *(const ull*)(wr + 6);
            ull h0 = pack2(hr[0], hr[0]);
            ull h1 = pack2(hr[1], hr[1]);
            ull h2 = pack2(hr[2], hr[2]);
            ull h3 = pack2(hr[3], hr[3]);
            acc[0]  = fma2(w0, h0, acc[0]);
            acc[1]  = fma2(w0, h1, acc[1]);
            acc[2]  = fma2(w0, h2, acc[2]);
            acc[3]  = fma2(w0, h3, acc[3]);
            acc[4]  = fma2(w1, h0, acc[4]);
            acc[5]  = fma2(w1, h1, acc[5]);
            acc[6]  = fma2(w1, h2, acc[6]);
            acc[7]  = fma2(w1, h3, acc[7]);
            acc[8]  = fma2(w2, h0, acc[8]);
            acc[9]  = fma2(w2, h1, acc[9]);
            acc[10] = fma2(w2, h2, acc[10]);
            acc[11] = fma2(w2, h3, acc[11]);
            acc[12] = fma2(w3, h0, acc[12]);
            acc[13] = fma2(w3, h1, acc[13]);
            acc[14] = fma2(w3, h2, acc[14]);
            acc[15] = fma2(w3, h3, acc[15]);
        }

#pragma unroll
        for (int i = 0; i < 16; i++) {
            acc[i] = add2(acc[i], __shfl_xor_sync(0xffffffffu, acc[i], 8));
            acc[i] = add2(acc[i], __shfl_xor_sync(0xffffffffu, acc[i], 16));
        }
        if (lane < 8) {
#pragma unroll
            for (int i = 0; i < 16; i++)
                red[(wid * 8 + grp) * 17 + ((i >> 2) * 4 + (i & 3))] = acc[i];
        }
        __syncthreads();

        if (tid < 128) {
            ull s = red[rgrp * 17 + rslot];
#pragma unroll
            for (int w = 1; w < 8; w++)
                s = add2(s, red[(w * 8 + rgrp) * 17 + rslot]);
            s = add2(s, xg2);
            float2 g = unpack2(s);
            gsm[(2 * cp) * 16 + rb]     = g.x;
            gsm[(2 * cp + 1) * 16 + rb] = g.y;
        }
        __syncthreads();

        // gates + state update (64 threads) — ONLY the 256B Hbuf store in the
        // fence window; Y goes to the smem ring.
        if (tid < 64) {
            int d2 = tid >> 4, bb = tid & 15;
            float gi = gsm[(0 * 4 + d2) * 16 + bb];
            float gf = gsm[(1 * 4 + d2) * 16 + bb];
            float gg = gsm[(2 * 4 + d2) * 16 + bb];
            float go = gsm[(3 * 4 + d2) * 16 + bb];
            float iv = fast_sigmoid(gi);
            float fv = fast_sigmoid(gf);
            float gv = fast_tanh(gg);
            float ov = fast_sigmoid(go);
            float c = fv * csm[tid] + iv * gv;
            csm[tid] = c;
            float hval = ov * fast_tanh(c);
            Hbuf[(t & 1) * (DD * BB) + (cta * 4 + d2) * BB + bb] = hval;
            Ybuf[(t & 7) * 64 + bb * 4 + d2] = hval;
            __threadfence();   // drains just the 256B Hbuf store
        }
        __syncthreads();

        int* barT = bar + (size_t)t * (BAR_SLOTS * BAR_STRIDE);

        // arrive first...
        if (tid == 0) atomicAdd(&barT[myslot], 1);

        // ...then flush Y (coalesced, overlaps the barrier wait), every 8 steps
        if ((t & 7) == 7 && tid < 128) {
            float4 v = *(const float4*)&Ybuf[fj * 64 + fb * 4];
            *(float4*)&Y[((size_t)fb * TT + (t - 7 + fj)) * DD + cta * 4] = v;
        }

        // poll all 8 counters
        if (wid == 0) {
            int done;
            do {
                int v = (lane < BAR_SLOTS)
                          ? *(volatile int*)&barT[lane * BAR_STRIDE]
                          : (NC / BAR_SLOTS);
                done = __all_sync(0xffffffffu, v >= (NC / BAR_SLOTS));
            } while (!done);
        }
        __syncthreads();
    }
}

// ---------------------------------------------------------------------------
__global__ __launch_bounds__(256)
void add_skip(const float* __restrict__ a, const float* __restrict__ x,
              float* __restrict__ out, int n4)
{
    int i = blockIdx.x * blockDim.x + threadIdx.x;
    if (i < n4) {
        float4 va = ((const float4*)a)[i];
        float4 vx = ((const float4*)x)[i];
        float4 r;
        r.x = va.x + vx.x; r.y = va.y + vx.y;
        r.z = va.z + vx.z; r.w = va.w + vx.w;
        ((float4*)out)[i] = r;
    }
}

// ---------------------------------------------------------------------------
extern "C" void kernel_launch(void* const* d_in, const int* in_sizes, int n_in,
                              void* d_out, int out_size)
{
    const float* x    = (const float*)d_in[0];
    const float* Wx   = (const float*)d_in[1];
    const float* Wh   = (const float*)d_in[2];
    const float* bias = (const float*)d_in[3];
    float* out = (float*)d_out;

    const int smem_scan =
        (512 * SW + 512 * SH + 2 * (8 * 8 * 17) + 256 + 64 + 512) * 4;
    cudaFuncSetAttribute(lstm_scan, cudaFuncAttributeMaxDynamicSharedMemorySize, smem_scan);

    void *xg_p, *y0_p, *y1_p, *h_p, *bar_p;
    cudaGetSymbolAddress(&xg_p, g_xg);
    cudaGetSymbolAddress(&y0_p, g_Y0);
    cudaGetSymbolAddress(&y1_p, g_Y1);
    cudaGetSymbolAddress(&h_p,  g_H);
    cudaGetSymbolAddress(&bar_p, g_bar);
    float* XG = (float*)xg_p;
    float* Y0 = (float*)y0_p;
    float* Y1 = (float*)y1_p;
    float* Hb = (float*)h_p;
    int*  BAR = (int*)bar_p;

    const size_t bar_bytes = (size_t)TT * BAR_SLOTS * BAR_STRIDE * sizeof(int);

    dim3 gg(GG / 128, TT / 128, BB);

    // ---- layer 0 ----
    gemm_xw<<<gg, 256>>>(x, Wx, bias, XG);
    cudaMemsetAsync(BAR, 0, bar_bytes, 0);
    cudaMemsetAsync(Hb, 0, 2 * DD * BB * sizeof(float), 0);
    lstm_scan<<<NC, SCAN_THREADS, smem_scan>>>(XG, Wh, Y0, Hb, BAR);

    // ---- layer 1 ----
    gemm_xw<<<gg, 256>>>(Y0, Wx + (size_t)DD * GG, bias + GG, XG);
    cudaMemsetAsync(BAR, 0, bar_bytes, 0);
    cudaMemsetAsync(Hb, 0, 2 * DD * BB * sizeof(float), 0);
    lstm_scan<<<NC, SCAN_THREADS, smem_scan>>>(XG, Wh + (size_t)DD * GG, Y1, Hb, BAR);

    // ---- residual skip ----
    int n4 = (BB * TT * DD) / 4;
    add_skip<<<n4 / 256, 256>>>(Y1, x, out, n4);
}